// round 12
// baseline (speedup 1.0000x reference)
#include <cuda_runtime.h>
#include <float.h>

#define BATCH 2
#define CH 64
#define H 480
#define W 480
#define HW (H * W)            // 230400
#define HC 960
#define WC 960
#define HWC (HC * WC)         // 921600
#define NQUAD (BATCH * H * (W / 4))   // 115200 quads per kind
#define WARPS_PER_KIND (NQUAD / 16)   // 7200
#define QUADS_PER_B (H * (W / 4))     // 57600
#define LIST_MAX 32768

#define NBLK 592      // 4 blocks/SM x 148 SMs -> all resident (barrier-safe)
#define NA 400        // role A blocks: LR outputs
#define NB (NBLK - NA)// role B blocks: pool + cen outputs

// ---------------- device scratch (zero at load; each call restores the
// all-zero state: pool zeroes cen winner cells; writers zero their winner
// grids; counters reset in-kernel). Barrier sense counters are monotone
// (pure sync state; never affects work or output). ------------------------
// Encoding: winner grids store (point_idx + 1); 0 = empty.
//           pooled grids store (slot + 1);      0 = empty.
__device__ int      g_win_l[BATCH * HW];
__device__ int      g_win_r[BATCH * HW];
__device__ int      g_win_lc[BATCH * HWC];
__device__ int      g_win_rc[BATCH * HWC];
__device__ int      g_pwin_lc[BATCH * HW];
__device__ int      g_pwin_rc[BATCH * HW];
__device__ int      g_list_lc[LIST_MAX];
__device__ int      g_list_rc[LIST_MAX];
__device__ int      g_cnt[2];
__device__ float    g_pf_lc[LIST_MAX * CH];   // pooled 64-ch features, compact
__device__ float    g_pf_rc[LIST_MAX * CH];
__device__ unsigned g_bar_cnt1;               // returns to 0 each call
__device__ unsigned g_bar_cnt2;
__device__ unsigned g_sense1;                 // monotone across calls
__device__ unsigned g_sense2;

#define CLAIM_TAG 0x7FFFFFFF

// sense-reversal grid barrier over `n` co-resident blocks.
__device__ __forceinline__ void gbar(unsigned* cnt, volatile unsigned* sense,
                                     unsigned n, unsigned target) {
    __syncthreads();
    if (threadIdx.x == 0) {
        __threadfence();
        if (atomicAdd(cnt, 1) == n - 1) {
            *cnt = 0;                       // next use is next call (safe)
            atomicAdd((unsigned*)sense, 1); // release
        } else {
            while ((int)(*sense - target) < 0) { }
        }
        __threadfence();
    }
    __syncthreads();
}

// resolve one occupied pooled cell: 2x2 max over 64 channels; zero the 4
// cen winner cells (this warp is their sole owner).
__device__ void pool_cell(int e, int n0, const float* __restrict__ fLC,
                          const float* __restrict__ fRC, int lane) {
    const float* feat;
    const int* wingrid;
    float* pf;
    int slot, cellp;
    if (e < n0) {
        slot = e; cellp = g_list_lc[e];
        feat = fLC; pf = g_pf_lc; wingrid = g_win_lc;
    } else {
        slot = e - n0; cellp = g_list_rc[slot];
        feat = fRC; pf = g_pf_rc; wingrid = g_win_rc;
    }
    int b = cellp / HW, sp = cellp % HW;
    int yp = sp / W, xp = sp % W;
    const int* winc = wingrid + (size_t)b * HWC + (2 * yp) * WC + 2 * xp;
    int w0 = winc[0], w1 = winc[1], w2 = winc[WC], w3 = winc[WC + 1];
    if (lane == 0) {
        int2 z = make_int2(0, 0);
        *(int2*)winc = z;
        *(int2*)(winc + WC) = z;
    }
    bool full = (w0 > 0) && (w1 > 0) && (w2 > 0) && (w3 > 0);
#pragma unroll
    for (int h = 0; h < 2; h++) {
        int c = lane + 32 * h;
        float m = full ? -FLT_MAX : 0.0f;
        if (w0 > 0) m = fmaxf(m, __ldg(&feat[(size_t)(w0 - 1) * CH + c]));
        if (w1 > 0) m = fmaxf(m, __ldg(&feat[(size_t)(w1 - 1) * CH + c]));
        if (w2 > 0) m = fmaxf(m, __ldg(&feat[(size_t)(w2 - 1) * CH + c]));
        if (w3 > 0) m = fmaxf(m, __ldg(&feat[(size_t)(w3 - 1) * CH + c]));
        pf[(size_t)slot * CH + c] = m;
    }
}

// streaming writer body. Warp layout: lanes 0-15 = chunk 0 of 16 consecutive
// quads, lanes 16-31 = chunk 1 of the SAME quads. After all lanes load the
// winner quad, __syncwarp, then chunk-0 lanes zero it (cleanup folded in).
__device__ __forceinline__ void fused_body(int kind, int warp_in_kind,
                                           int lane,
                                           const float4* __restrict__ f4,
                                           int* __restrict__ win,
                                           float* __restrict__ out) {
    int q = warp_in_kind * 16 + (lane & 15);   // quad index within kind
    int chunk = lane >> 4;
    int b = q / QUADS_PER_B;
    int s = (q - b * QUADS_PER_B) * 4;         // contiguous over (y,x4)

    const size_t GRID = (size_t)CH * HW;
    const size_t OUT_R = (size_t)BATCH * GRID;
    const size_t OUT_CAT = 2 * OUT_R;
    const float4 z4 = make_float4(0.f, 0.f, 0.f, 0.f);

    size_t choff = (size_t)(chunk * 32) * HW + s;
    float* cat = out + OUT_CAT + (size_t)b * 4 * GRID;
    float* o1;
    float* o2 = nullptr;
    if (kind == 0) {
        o1 = out + (size_t)b * GRID + choff;
        o2 = cat + choff;
    } else if (kind == 1) {
        o1 = out + OUT_R + (size_t)b * GRID + choff;
        o2 = cat + (size_t)2 * CH * HW + choff;
    } else if (kind == 2) {
        o1 = cat + (size_t)CH * HW + choff;
    } else {
        o1 = cat + (size_t)3 * CH * HW + choff;
    }

    int4* wp = (int4*)(win + b * HW + s);
    int4 w = *wp;
    bool any = (w.x | w.y | w.z | w.w) != 0;
    __syncwarp();                               // all lanes have loaded
    if (any && chunk == 0) *wp = make_int4(0, 0, 0, 0);  // restore zero state
    const float4* f4b = f4 - 16;                // values are idx+1

#pragma unroll
    for (int sub = 0; sub < 8; sub++) {
        float4 c0 = z4, c1 = z4, c2 = z4, c3 = z4;
        if (any) {
            int fo = chunk * 8 + sub;
            if (w.x > 0) c0 = __ldg(&f4b[(size_t)w.x * 16 + fo]);
            if (w.y > 0) c1 = __ldg(&f4b[(size_t)w.y * 16 + fo]);
            if (w.z > 0) c2 = __ldg(&f4b[(size_t)w.z * 16 + fo]);
            if (w.w > 0) c3 = __ldg(&f4b[(size_t)w.w * 16 + fo]);
        }
        float4 v0 = make_float4(c0.x, c1.x, c2.x, c3.x);
        float4 v1 = make_float4(c0.y, c1.y, c2.y, c3.y);
        float4 v2 = make_float4(c0.z, c1.z, c2.z, c3.z);
        float4 v3 = make_float4(c0.w, c1.w, c2.w, c3.w);
        size_t co = (size_t)(sub * 4) * HW;
        __stcs((float4*)(o1 + co), v0);
        __stcs((float4*)(o1 + co + HW), v1);
        __stcs((float4*)(o1 + co + 2 * (size_t)HW), v2);
        __stcs((float4*)(o1 + co + 3 * (size_t)HW), v3);
        if (o2) {
            __stcs((float4*)(o2 + co), v0);
            __stcs((float4*)(o2 + co + HW), v1);
            __stcs((float4*)(o2 + co + 2 * (size_t)HW), v2);
            __stcs((float4*)(o2 + co + 3 * (size_t)HW), v3);
        }
    }
}

__global__ void __launch_bounds__(256, 4)
mega(const int* __restrict__ cL, int pL, const int* __restrict__ cR, int pR,
     const int* __restrict__ cLC, int pLC, const int* __restrict__ cRC, int pRC,
     const float4* __restrict__ fL4, const float4* __restrict__ fR4,
     const float* __restrict__ fLC, const float* __restrict__ fRC,
     float* __restrict__ out) {
    // stable pre-call sense values (previous call fully completed)
    unsigned base1 = g_sense1;
    unsigned base2 = g_sense2;

    // ---- phase 1: scatter all 4 point sets (last point index wins) ----
    int PT = pL + pR + pLC + pRC;
    for (int i = blockIdx.x * 256 + threadIdx.x; i < PT; i += NBLK * 256) {
        if (i < pL) {
            int4 c = __ldg((const int4*)(cL + 4 * i));
            atomicMax(&g_win_l[c.x * HW + c.z * W + c.w], i + 1);
        } else if (i < pL + pR) {
            int j = i - pL;
            int4 c = __ldg((const int4*)(cR + 4 * j));
            atomicMax(&g_win_r[c.x * HW + c.z * W + c.w], j + 1);
        } else if (i < pL + pR + pLC) {
            int j = i - pL - pR;
            int4 c = __ldg((const int4*)(cLC + 4 * j));
            atomicMax(&g_win_lc[c.x * HWC + c.z * WC + c.w], j + 1);
            int cellp = c.x * HW + (c.z >> 1) * W + (c.w >> 1);
            if (atomicCAS(&g_pwin_lc[cellp], 0, CLAIM_TAG) == 0) {
                int e = atomicAdd(&g_cnt[0], 1);
                g_list_lc[e] = cellp;
                g_pwin_lc[cellp] = e + 1;
            }
        } else {
            int j = i - pL - pR - pLC;
            int4 c = __ldg((const int4*)(cRC + 4 * j));
            atomicMax(&g_win_rc[c.x * HWC + c.z * WC + c.w], j + 1);
            int cellp = c.x * HW + (c.z >> 1) * W + (c.w >> 1);
            if (atomicCAS(&g_pwin_rc[cellp], 0, CLAIM_TAG) == 0) {
                int e = atomicAdd(&g_cnt[1], 1);
                g_list_rc[e] = cellp;
                g_pwin_rc[cellp] = e + 1;
            }
        }
    }

    // ---- barrier 1: all blocks ----
    gbar(&g_bar_cnt1, &g_sense1, NBLK, base1 + 1);

    int lane = threadIdx.x & 31;
    if (blockIdx.x < NA) {
        // ---- role A: stream LR outputs (kinds 0,1) ----
        int aw = blockIdx.x * 8 + (threadIdx.x >> 5);
        for (int wt = aw; wt < 2 * WARPS_PER_KIND; wt += NA * 8) {
            int kind = wt / WARPS_PER_KIND;
            fused_body(kind, wt % WARPS_PER_KIND, lane,
                       kind == 0 ? fL4 : fR4,
                       kind == 0 ? g_win_l : g_win_r, out);
        }
    } else {
        // ---- role B: pool, barrier, stream cen outputs (kinds 2,3) ----
        int bblk = blockIdx.x - NA;
        int bw = bblk * 8 + (threadIdx.x >> 5);
        int n0 = g_cnt[0], n1 = g_cnt[1];
        for (int e = bw; e < n0 + n1; e += NB * 8)
            pool_cell(e, n0, fLC, fRC, lane);

        gbar(&g_bar_cnt2, &g_sense2, NB, base2 + 1);
        if (bblk == 0 && threadIdx.x == 0) { g_cnt[0] = 0; g_cnt[1] = 0; }

        for (int wt = bw; wt < 2 * WARPS_PER_KIND; wt += NB * 8) {
            int kind = 2 + wt / WARPS_PER_KIND;
            fused_body(kind, wt % WARPS_PER_KIND, lane,
                       kind == 2 ? (const float4*)g_pf_lc
                                 : (const float4*)g_pf_rc,
                       kind == 2 ? g_pwin_lc : g_pwin_rc, out);
        }
    }
}

extern "C" void kernel_launch(void* const* d_in, const int* in_sizes, int n_in,
                              void* d_out, int out_size) {
    const float* fRC = (const float*)d_in[0];
    const int*   cRC = (const int*)d_in[1];
    const float* fLC = (const float*)d_in[2];
    const int*   cLC = (const int*)d_in[3];
    const float* fL  = (const float*)d_in[4];
    const int*   cL  = (const int*)d_in[5];
    const float* fR  = (const float*)d_in[6];
    const int*   cR  = (const int*)d_in[7];
    float* out = (float*)d_out;

    int pRC = in_sizes[1] / 4;
    int pLC = in_sizes[3] / 4;
    int pL  = in_sizes[5] / 4;
    int pR  = in_sizes[7] / 4;

    mega<<<NBLK, 256>>>(cL, pL, cR, pR, cLC, pLC, cRC, pRC,
                        (const float4*)fL, (const float4*)fR, fLC, fRC, out);
}

// round 13
// speedup vs baseline: 1.2093x; 1.2093x over previous
#include <cuda_runtime.h>
#include <float.h>

#define BATCH 2
#define CH 64
#define H 480
#define W 480
#define HW (H * W)            // 230400
#define HC 960
#define WC 960
#define HWC (HC * WC)         // 921600
#define NQUAD (BATCH * H * (W / 4))   // 115200 quads per kind
#define WARPS_PER_KIND (NQUAD / 16)   // 7200
#define QUADS_PER_B (H * (W / 4))     // 57600
#define LIST_MAX 32768

// ---------------- device scratch (zero at load; each call restores the
// all-zero state: pool_feat zeroes cen winner cells; the fused kernels zero
// the 480 winner / pooled grids as they consume them) -----------------------
// Encoding: winner grids store (point_idx + 1); 0 = empty.
//           pooled grids store (slot + 1);      0 = empty.
__device__ int   g_win_l[BATCH * HW];
__device__ int   g_win_r[BATCH * HW];
__device__ int   g_win_lc[BATCH * HWC];
__device__ int   g_win_rc[BATCH * HWC];
__device__ int   g_pwin_lc[BATCH * HW];
__device__ int   g_pwin_rc[BATCH * HW];
__device__ int   g_list_lc[LIST_MAX];
__device__ int   g_list_rc[LIST_MAX];
__device__ int   g_cnt[2];
__device__ float g_pf_lc[LIST_MAX * CH];     // pooled 64-ch features, compact
__device__ float g_pf_rc[LIST_MAX * CH];

#define CLAIM_TAG 0x7FFFFFFF

// last point index wins == JAX sequential .set semantics
__global__ void scatter_LR(const int* __restrict__ cL, int pL,
                           const int* __restrict__ cR, int pR) {
    int i = blockIdx.x * blockDim.x + threadIdx.x;
    if (i < pL) {
        int4 c = __ldg((const int4*)(cL + 4 * i));
        atomicMax(&g_win_l[c.x * HW + c.z * W + c.w], i + 1);
    } else if (i < pL + pR) {
        int j = i - pL;
        int4 c = __ldg((const int4*)(cR + 4 * j));
        atomicMax(&g_win_r[c.x * HW + c.z * W + c.w], j + 1);
    }
    cudaTriggerProgrammaticLaunchCompletion();
}

__global__ void scatter_cen(const int* __restrict__ cLC, int pLC,
                            const int* __restrict__ cRC, int pRC) {
    int i = blockIdx.x * blockDim.x + threadIdx.x;
    if (i < pLC) {
        int4 c = __ldg((const int4*)(cLC + 4 * i));
        atomicMax(&g_win_lc[c.x * HWC + c.z * WC + c.w], i + 1);
        int cellp = c.x * HW + (c.z >> 1) * W + (c.w >> 1);
        if (atomicCAS(&g_pwin_lc[cellp], 0, CLAIM_TAG) == 0) {
            int e = atomicAdd(&g_cnt[0], 1);
            g_list_lc[e] = cellp;
            g_pwin_lc[cellp] = e + 1;
        }
    } else if (i < pLC + pRC) {
        int j = i - pLC;
        int4 c = __ldg((const int4*)(cRC + 4 * j));
        atomicMax(&g_win_rc[c.x * HWC + c.z * WC + c.w], j + 1);
        int cellp = c.x * HW + (c.z >> 1) * W + (c.w >> 1);
        if (atomicCAS(&g_pwin_rc[cellp], 0, CLAIM_TAG) == 0) {
            int e = atomicAdd(&g_cnt[1], 1);
            g_list_rc[e] = cellp;
            g_pwin_rc[cellp] = e + 1;
        }
    }
    cudaTriggerProgrammaticLaunchCompletion();
}

// one warp per occupied pooled cell: resolve 2x2 max over 64 channels.
// Pool windows partition the cen grid; this warp solely owns its 4 winner
// cells and zeroes them (cen winner-grid cleanup folded in).
__global__ void pool_feat(const float* __restrict__ fLC,
                          const float* __restrict__ fRC, int pLC) {
    cudaGridDependencySynchronize();            // wait for scatter_cen data
    int g = (blockIdx.x * blockDim.x + threadIdx.x) >> 5;
    int lane = threadIdx.x & 31;
    const float* feat;
    const int* wingrid;
    float* pf;
    int e, cellp;
    bool active = true;
    if (g < pLC) {
        e = g;
        if (e >= g_cnt[0]) active = false;
        cellp = active ? g_list_lc[e] : 0;
        feat = fLC; pf = g_pf_lc; wingrid = g_win_lc;
    } else {
        e = g - pLC;
        if (e >= g_cnt[1]) active = false;
        cellp = active ? g_list_rc[e] : 0;
        feat = fRC; pf = g_pf_rc; wingrid = g_win_rc;
    }
    if (active) {
        int b = cellp / HW, sp = cellp % HW;
        int yp = sp / W, xp = sp % W;
        const int* winc = wingrid + (size_t)b * HWC + (2 * yp) * WC + 2 * xp;
        int w0 = winc[0], w1 = winc[1], w2 = winc[WC], w3 = winc[WC + 1];
        if (lane == 0) {   // zero the cen winner cells (sole owner)
            int2 z = make_int2(0, 0);
            *(int2*)winc = z;
            *(int2*)(winc + WC) = z;
        }
        bool full = (w0 > 0) && (w1 > 0) && (w2 > 0) && (w3 > 0);
#pragma unroll
        for (int h = 0; h < 2; h++) {
            int c = lane + 32 * h;
            float m = full ? -FLT_MAX : 0.0f;
            if (w0 > 0) m = fmaxf(m, __ldg(&feat[(size_t)(w0 - 1) * CH + c]));
            if (w1 > 0) m = fmaxf(m, __ldg(&feat[(size_t)(w1 - 1) * CH + c]));
            if (w2 > 0) m = fmaxf(m, __ldg(&feat[(size_t)(w2 - 1) * CH + c]));
            if (w3 > 0) m = fmaxf(m, __ldg(&feat[(size_t)(w3 - 1) * CH + c]));
            pf[(size_t)e * CH + c] = m;
        }
    }
    cudaTriggerProgrammaticLaunchCompletion();
}

// shared body. Warp layout: lanes 0-15 = chunk 0 of 16 consecutive quads,
// lanes 16-31 = chunk 1 of the SAME quads. After all lanes load the winner
// quad, __syncwarp, then lanes 0-15 zero it (scratch cleanup folded in).
// l2keep: write o1 with plain write-back stores so its lines stay resident
// in L2 across graph replays (steady-state DRAM-write elision).
__device__ __forceinline__ void fused_body(int kind, int warp_in_kind,
                                           int lane, bool l2keep,
                                           const float4* __restrict__ f4,
                                           int* __restrict__ win,
                                           float* __restrict__ out) {
    int q = warp_in_kind * 16 + (lane & 15);   // quad index within kind
    int chunk = lane >> 4;
    int b = q / QUADS_PER_B;
    int s = (q - b * QUADS_PER_B) * 4;         // contiguous over (y,x4)

    const size_t GRID = (size_t)CH * HW;
    const size_t OUT_R = (size_t)BATCH * GRID;
    const size_t OUT_CAT = 2 * OUT_R;
    const float4 z4 = make_float4(0.f, 0.f, 0.f, 0.f);

    size_t choff = (size_t)(chunk * 32) * HW + s;
    float* cat = out + OUT_CAT + (size_t)b * 4 * GRID;
    float* o1;
    float* o2 = nullptr;
    if (kind == 0) {
        o1 = out + (size_t)b * GRID + choff;
        o2 = cat + choff;
    } else if (kind == 1) {
        o1 = out + OUT_R + (size_t)b * GRID + choff;
        o2 = cat + (size_t)2 * CH * HW + choff;
    } else if (kind == 2) {
        o1 = cat + (size_t)CH * HW + choff;
    } else {
        o1 = cat + (size_t)3 * CH * HW + choff;
    }

    int4* wp = (int4*)(win + b * HW + s);
    int4 w = *wp;
    bool any = (w.x | w.y | w.z | w.w) != 0;
    __syncwarp();                               // all lanes have loaded
    if (any && chunk == 0) *wp = make_int4(0, 0, 0, 0);  // restore zero state
    const float4* f4b = f4 - 16;                // values are idx+1

#pragma unroll
    for (int sub = 0; sub < 8; sub++) {
        float4 c0 = z4, c1 = z4, c2 = z4, c3 = z4;
        if (any) {
            int fo = chunk * 8 + sub;
            if (w.x > 0) c0 = __ldg(&f4b[(size_t)w.x * 16 + fo]);
            if (w.y > 0) c1 = __ldg(&f4b[(size_t)w.y * 16 + fo]);
            if (w.z > 0) c2 = __ldg(&f4b[(size_t)w.z * 16 + fo]);
            if (w.w > 0) c3 = __ldg(&f4b[(size_t)w.w * 16 + fo]);
        }
        float4 v0 = make_float4(c0.x, c1.x, c2.x, c3.x);
        float4 v1 = make_float4(c0.y, c1.y, c2.y, c3.y);
        float4 v2 = make_float4(c0.z, c1.z, c2.z, c3.z);
        float4 v3 = make_float4(c0.w, c1.w, c2.w, c3.w);
        size_t co = (size_t)(sub * 4) * HW;
        if (l2keep) {   // write-back stores: lines stay dirty-resident in L2
            *(float4*)(o1 + co) = v0;
            *(float4*)(o1 + co + HW) = v1;
            *(float4*)(o1 + co + 2 * (size_t)HW) = v2;
            *(float4*)(o1 + co + 3 * (size_t)HW) = v3;
        } else {
            __stcs((float4*)(o1 + co), v0);
            __stcs((float4*)(o1 + co + HW), v1);
            __stcs((float4*)(o1 + co + 2 * (size_t)HW), v2);
            __stcs((float4*)(o1 + co + 3 * (size_t)HW), v3);
        }
        if (o2) {
            __stcs((float4*)(o2 + co), v0);
            __stcs((float4*)(o2 + co + HW), v1);
            __stcs((float4*)(o2 + co + 2 * (size_t)HW), v2);
            __stcs((float4*)(o2 + co + 3 * (size_t)HW), v3);
        }
    }
}

__global__ void __launch_bounds__(256)
fused_LR(const float4* __restrict__ fL4, const float4* __restrict__ fR4,
         float* __restrict__ out) {
    int t = blockIdx.x * blockDim.x + threadIdx.x;
    int gw = t >> 5, lane = t & 31;
    int kind = gw / WARPS_PER_KIND;            // 0 or 1
    cudaGridDependencySynchronize();           // wait for scatter_LR data
    fused_body(kind, gw % WARPS_PER_KIND, lane, kind == 0 /*l2keep lidar*/,
               kind == 0 ? fL4 : fR4,
               kind == 0 ? g_win_l : g_win_r, out);
}

__global__ void __launch_bounds__(256)
fused_cen(float* __restrict__ out) {
    int t = blockIdx.x * blockDim.x + threadIdx.x;
    int gw = t >> 5, lane = t & 31;
    int kind = 2 + gw / WARPS_PER_KIND;        // 2 or 3
    cudaGridDependencySynchronize();           // wait for pool_feat data
    if (t == 0) { g_cnt[0] = 0; g_cnt[1] = 0; }  // pool_feat already consumed
    fused_body(kind, gw % WARPS_PER_KIND, lane, false,
               kind == 2 ? (const float4*)g_pf_lc : (const float4*)g_pf_rc,
               kind == 2 ? g_pwin_lc : g_pwin_rc, out);
}

// helper: launch with PDL (programmatic stream serialization) on a stream
template <typename... Args>
static void launch_pdl(void (*kern)(Args...), dim3 grid, dim3 block,
                       cudaStream_t stream, Args... args) {
    cudaLaunchConfig_t cfg = {};
    cfg.gridDim = grid;
    cfg.blockDim = block;
    cfg.dynamicSmemBytes = 0;
    cfg.stream = stream;
    cudaLaunchAttribute attr[1];
    attr[0].id = cudaLaunchAttributeProgrammaticStreamSerialization;
    attr[0].val.programmaticStreamSerializationAllowed = 1;
    cfg.attrs = attr;
    cfg.numAttrs = 1;
    cudaLaunchKernelEx(&cfg, kern, args...);
}

extern "C" void kernel_launch(void* const* d_in, const int* in_sizes, int n_in,
                              void* d_out, int out_size) {
    const float* fRC = (const float*)d_in[0];
    const int*   cRC = (const int*)d_in[1];
    const float* fLC = (const float*)d_in[2];
    const int*   cLC = (const int*)d_in[3];
    const float* fL  = (const float*)d_in[4];
    const int*   cL  = (const int*)d_in[5];
    const float* fR  = (const float*)d_in[6];
    const int*   cR  = (const int*)d_in[7];
    float* out = (float*)d_out;

    int pRC = in_sizes[1] / 4;
    int pLC = in_sizes[3] / 4;
    int pL  = in_sizes[5] / 4;
    int pR  = in_sizes[7] / 4;

    // Two dependency chains, fork-join around stream 0 for graph capture.
    // Stream/event creation is host-only (capture-time, not replay-time).
    cudaStream_t s1;
    cudaStreamCreateWithFlags(&s1, cudaStreamNonBlocking);
    cudaEvent_t e_fork, e_join;
    cudaEventCreateWithFlags(&e_fork, cudaEventDisableTiming);
    cudaEventCreateWithFlags(&e_join, cudaEventDisableTiming);

    cudaEventRecord(e_fork, 0);
    cudaStreamWaitEvent(s1, e_fork, 0);

    // side chain: cen scatter -> pool -> fused_cen (PDL between links)
    scatter_cen<<<(pLC + pRC + 255) / 256, 256, 0, s1>>>(cLC, pLC, cRC, pRC);
    int pw = pLC + pRC;  // upper bound on occupied pooled cells (both kinds)
    launch_pdl(pool_feat, dim3((pw * 32 + 255) / 256), dim3(256), s1,
               fLC, fRC, pLC);
    launch_pdl(fused_cen, dim3(2 * WARPS_PER_KIND * 32 / 256), dim3(256), s1,
               out);
    cudaEventRecord(e_join, s1);

    // main chain: LR scatter -> fused_LR (PDL link)
    scatter_LR<<<(pL + pR + 255) / 256, 256>>>(cL, pL, cR, pR);
    launch_pdl(fused_LR, dim3(2 * WARPS_PER_KIND * 32 / 256), dim3(256),
               (cudaStream_t)0, (const float4*)fL, (const float4*)fR, out);

    cudaStreamWaitEvent(0, e_join, 0);

    cudaEventDestroy(e_fork);
    cudaEventDestroy(e_join);
    cudaStreamDestroy(s1);
}

// round 15
// speedup vs baseline: 1.2937x; 1.0697x over previous
#include <cuda_runtime.h>
#include <float.h>

#define BATCH 2
#define CH 64
#define H 480
#define W 480
#define HW (H * W)            // 230400
#define HC 960
#define WC 960
#define HWC (HC * WC)         // 921600
#define NQUAD (BATCH * H * (W / 4))   // 115200 quads per kind
#define WARPS_PER_KIND (NQUAD / 16)   // 7200
#define QUADS_PER_B (H * (W / 4))     // 57600
#define LIST_MAX 32768
#define SCB 4                 // points per scatter thread (MLP batching)

// ---------------- device scratch (zero at load; each call restores the
// all-zero state: pool_feat zeroes cen winner cells; the fused kernels zero
// the 480 winner / pooled grids as they consume them) -----------------------
// Encoding: winner grids store (point_idx + 1); 0 = empty.
//           pooled grids store (slot + 1);      0 = empty.
__device__ int   g_win_l[BATCH * HW];
__device__ int   g_win_r[BATCH * HW];
__device__ int   g_win_lc[BATCH * HWC];
__device__ int   g_win_rc[BATCH * HWC];
__device__ int   g_pwin_lc[BATCH * HW];
__device__ int   g_pwin_rc[BATCH * HW];
__device__ int   g_list_lc[LIST_MAX];
__device__ int   g_list_rc[LIST_MAX];
__device__ int   g_cnt[2];
__device__ float g_pf_lc[LIST_MAX * CH];     // pooled 64-ch features, compact
__device__ float g_pf_rc[LIST_MAX * CH];

#define CLAIM_TAG 0x7FFFFFFF

// last point index wins == JAX sequential .set semantics.
// SCB points per thread; the SCB chains are independent -> MLP ~ SCB.
__global__ void scatter_LR(const int* __restrict__ cL, int pL,
                           const int* __restrict__ cR, int pR) {
    int base = (blockIdx.x * blockDim.x + threadIdx.x) * SCB;
#pragma unroll
    for (int k = 0; k < SCB; k++) {
        int i = base + k;
        if (i < pL) {
            int4 c = __ldg((const int4*)(cL + 4 * i));
            atomicMax(&g_win_l[c.x * HW + c.z * W + c.w], i + 1);
        } else if (i < pL + pR) {
            int j = i - pL;
            int4 c = __ldg((const int4*)(cR + 4 * j));
            atomicMax(&g_win_r[c.x * HW + c.z * W + c.w], j + 1);
        }
    }
    cudaTriggerProgrammaticLaunchCompletion();
}

__global__ void scatter_cen(const int* __restrict__ cLC, int pLC,
                            const int* __restrict__ cRC, int pRC) {
    int base = (blockIdx.x * blockDim.x + threadIdx.x) * SCB;
#pragma unroll
    for (int k = 0; k < SCB; k++) {
        int i = base + k;
        if (i < pLC) {
            int4 c = __ldg((const int4*)(cLC + 4 * i));
            atomicMax(&g_win_lc[c.x * HWC + c.z * WC + c.w], i + 1);
            int cellp = c.x * HW + (c.z >> 1) * W + (c.w >> 1);
            if (atomicCAS(&g_pwin_lc[cellp], 0, CLAIM_TAG) == 0) {
                int e = atomicAdd(&g_cnt[0], 1);
                g_list_lc[e] = cellp;
                g_pwin_lc[cellp] = e + 1;
            }
        } else if (i < pLC + pRC) {
            int j = i - pLC;
            int4 c = __ldg((const int4*)(cRC + 4 * j));
            atomicMax(&g_win_rc[c.x * HWC + c.z * WC + c.w], j + 1);
            int cellp = c.x * HW + (c.z >> 1) * W + (c.w >> 1);
            if (atomicCAS(&g_pwin_rc[cellp], 0, CLAIM_TAG) == 0) {
                int e = atomicAdd(&g_cnt[1], 1);
                g_list_rc[e] = cellp;
                g_pwin_rc[cellp] = e + 1;
            }
        }
    }
    cudaTriggerProgrammaticLaunchCompletion();
}

// one warp per occupied pooled cell: resolve 2x2 max over 64 channels.
// Pool windows partition the cen grid; this warp solely owns its 4 winner
// cells and zeroes them (cen winner-grid cleanup folded in).
__global__ void pool_feat(const float* __restrict__ fLC,
                          const float* __restrict__ fRC, int pLC) {
    cudaGridDependencySynchronize();            // wait for scatter_cen data
    int g = (blockIdx.x * blockDim.x + threadIdx.x) >> 5;
    int lane = threadIdx.x & 31;
    const float* feat;
    const int* wingrid;
    float* pf;
    int e, cellp;
    bool active = true;
    if (g < pLC) {
        e = g;
        if (e >= g_cnt[0]) active = false;
        cellp = active ? g_list_lc[e] : 0;
        feat = fLC; pf = g_pf_lc; wingrid = g_win_lc;
    } else {
        e = g - pLC;
        if (e >= g_cnt[1]) active = false;
        cellp = active ? g_list_rc[e] : 0;
        feat = fRC; pf = g_pf_rc; wingrid = g_win_rc;
    }
    if (active) {
        int b = cellp / HW, sp = cellp % HW;
        int yp = sp / W, xp = sp % W;
        const int* winc = wingrid + (size_t)b * HWC + (2 * yp) * WC + 2 * xp;
        int w0 = winc[0], w1 = winc[1], w2 = winc[WC], w3 = winc[WC + 1];
        if (lane == 0) {   // zero the cen winner cells (sole owner)
            int2 z = make_int2(0, 0);
            *(int2*)winc = z;
            *(int2*)(winc + WC) = z;
        }
        bool full = (w0 > 0) && (w1 > 0) && (w2 > 0) && (w3 > 0);
#pragma unroll
        for (int h = 0; h < 2; h++) {
            int c = lane + 32 * h;
            float m = full ? -FLT_MAX : 0.0f;
            if (w0 > 0) m = fmaxf(m, __ldg(&feat[(size_t)(w0 - 1) * CH + c]));
            if (w1 > 0) m = fmaxf(m, __ldg(&feat[(size_t)(w1 - 1) * CH + c]));
            if (w2 > 0) m = fmaxf(m, __ldg(&feat[(size_t)(w2 - 1) * CH + c]));
            if (w3 > 0) m = fmaxf(m, __ldg(&feat[(size_t)(w3 - 1) * CH + c]));
            pf[(size_t)e * CH + c] = m;
        }
    }
    cudaTriggerProgrammaticLaunchCompletion();
}

// shared body. Warp layout: lanes 0-15 = chunk 0 of 16 consecutive quads,
// lanes 16-31 = chunk 1 of the SAME quads. After all lanes load the winner
// quad, __syncwarp, then lanes 0-15 zero it (scratch cleanup folded in).
__device__ __forceinline__ void fused_body(int kind, int warp_in_kind,
                                           int lane,
                                           const float4* __restrict__ f4,
                                           int* __restrict__ win,
                                           float* __restrict__ out) {
    int q = warp_in_kind * 16 + (lane & 15);   // quad index within kind
    int chunk = lane >> 4;
    int b = q / QUADS_PER_B;
    int s = (q - b * QUADS_PER_B) * 4;         // contiguous over (y,x4)

    const size_t GRID = (size_t)CH * HW;
    const size_t OUT_R = (size_t)BATCH * GRID;
    const size_t OUT_CAT = 2 * OUT_R;
    const float4 z4 = make_float4(0.f, 0.f, 0.f, 0.f);

    size_t choff = (size_t)(chunk * 32) * HW + s;
    float* cat = out + OUT_CAT + (size_t)b * 4 * GRID;
    float* o1;
    float* o2 = nullptr;
    if (kind == 0) {
        o1 = out + (size_t)b * GRID + choff;
        o2 = cat + choff;
    } else if (kind == 1) {
        o1 = out + OUT_R + (size_t)b * GRID + choff;
        o2 = cat + (size_t)2 * CH * HW + choff;
    } else if (kind == 2) {
        o1 = cat + (size_t)CH * HW + choff;
    } else {
        o1 = cat + (size_t)3 * CH * HW + choff;
    }

    int4* wp = (int4*)(win + b * HW + s);
    int4 w = *wp;
    bool any = (w.x | w.y | w.z | w.w) != 0;
    __syncwarp();                               // all lanes have loaded
    if (any && chunk == 0) *wp = make_int4(0, 0, 0, 0);  // restore zero state
    const float4* f4b = f4 - 16;                // values are idx+1

#pragma unroll
    for (int sub = 0; sub < 8; sub++) {
        float4 c0 = z4, c1 = z4, c2 = z4, c3 = z4;
        if (any) {
            int fo = chunk * 8 + sub;
            if (w.x > 0) c0 = __ldg(&f4b[(size_t)w.x * 16 + fo]);
            if (w.y > 0) c1 = __ldg(&f4b[(size_t)w.y * 16 + fo]);
            if (w.z > 0) c2 = __ldg(&f4b[(size_t)w.z * 16 + fo]);
            if (w.w > 0) c3 = __ldg(&f4b[(size_t)w.w * 16 + fo]);
        }
        float4 v0 = make_float4(c0.x, c1.x, c2.x, c3.x);
        float4 v1 = make_float4(c0.y, c1.y, c2.y, c3.y);
        float4 v2 = make_float4(c0.z, c1.z, c2.z, c3.z);
        float4 v3 = make_float4(c0.w, c1.w, c2.w, c3.w);
        size_t co = (size_t)(sub * 4) * HW;
        __stcs((float4*)(o1 + co), v0);
        __stcs((float4*)(o1 + co + HW), v1);
        __stcs((float4*)(o1 + co + 2 * (size_t)HW), v2);
        __stcs((float4*)(o1 + co + 3 * (size_t)HW), v3);
        if (o2) {
            __stcs((float4*)(o2 + co), v0);
            __stcs((float4*)(o2 + co + HW), v1);
            __stcs((float4*)(o2 + co + 2 * (size_t)HW), v2);
            __stcs((float4*)(o2 + co + 3 * (size_t)HW), v3);
        }
    }
}

__global__ void __launch_bounds__(256)
fused_LR(const float4* __restrict__ fL4, const float4* __restrict__ fR4,
         float* __restrict__ out) {
    int t = blockIdx.x * blockDim.x + threadIdx.x;
    int gw = t >> 5, lane = t & 31;
    int kind = gw / WARPS_PER_KIND;            // 0 or 1
    cudaGridDependencySynchronize();           // wait for scatter_LR data
    fused_body(kind, gw % WARPS_PER_KIND, lane,
               kind == 0 ? fL4 : fR4,
               kind == 0 ? g_win_l : g_win_r, out);
}

__global__ void __launch_bounds__(256)
fused_cen(float* __restrict__ out) {
    int t = blockIdx.x * blockDim.x + threadIdx.x;
    int gw = t >> 5, lane = t & 31;
    int kind = 2 + gw / WARPS_PER_KIND;        // 2 or 3
    cudaGridDependencySynchronize();           // wait for pool_feat data
    if (t == 0) { g_cnt[0] = 0; g_cnt[1] = 0; }  // pool_feat already consumed
    fused_body(kind, gw % WARPS_PER_KIND, lane,
               kind == 2 ? (const float4*)g_pf_lc : (const float4*)g_pf_rc,
               kind == 2 ? g_pwin_lc : g_pwin_rc, out);
}

// helper: launch with PDL (programmatic stream serialization) on a stream
template <typename... Args>
static void launch_pdl(void (*kern)(Args...), dim3 grid, dim3 block,
                       cudaStream_t stream, Args... args) {
    cudaLaunchConfig_t cfg = {};
    cfg.gridDim = grid;
    cfg.blockDim = block;
    cfg.dynamicSmemBytes = 0;
    cfg.stream = stream;
    cudaLaunchAttribute attr[1];
    attr[0].id = cudaLaunchAttributeProgrammaticStreamSerialization;
    attr[0].val.programmaticStreamSerializationAllowed = 1;
    cfg.attrs = attr;
    cfg.numAttrs = 1;
    cudaLaunchKernelEx(&cfg, kern, args...);
}

extern "C" void kernel_launch(void* const* d_in, const int* in_sizes, int n_in,
                              void* d_out, int out_size) {
    const float* fRC = (const float*)d_in[0];
    const int*   cRC = (const int*)d_in[1];
    const float* fLC = (const float*)d_in[2];
    const int*   cLC = (const int*)d_in[3];
    const float* fL  = (const float*)d_in[4];
    const int*   cL  = (const int*)d_in[5];
    const float* fR  = (const float*)d_in[6];
    const int*   cR  = (const int*)d_in[7];
    float* out = (float*)d_out;

    int pRC = in_sizes[1] / 4;
    int pLC = in_sizes[3] / 4;
    int pL  = in_sizes[5] / 4;
    int pR  = in_sizes[7] / 4;

    // Two dependency chains, fork-join around stream 0 for graph capture.
    // Stream/event creation is host-only (capture-time, not replay-time).
    cudaStream_t s1;
    cudaStreamCreateWithFlags(&s1, cudaStreamNonBlocking);
    cudaEvent_t e_fork, e_join;
    cudaEventCreateWithFlags(&e_fork, cudaEventDisableTiming);
    cudaEventCreateWithFlags(&e_join, cudaEventDisableTiming);

    cudaEventRecord(e_fork, 0);
    cudaStreamWaitEvent(s1, e_fork, 0);

    // side chain: cen scatter -> pool -> fused_cen (PDL between links)
    int tc = (pLC + pRC + SCB - 1) / SCB;
    scatter_cen<<<(tc + 255) / 256, 256, 0, s1>>>(cLC, pLC, cRC, pRC);
    int pw = pLC + pRC;  // upper bound on occupied pooled cells (both kinds)
    launch_pdl(pool_feat, dim3((pw * 32 + 255) / 256), dim3(256), s1,
               fLC, fRC, pLC);
    launch_pdl(fused_cen, dim3(2 * WARPS_PER_KIND * 32 / 256), dim3(256), s1,
               out);
    cudaEventRecord(e_join, s1);

    // main chain: LR scatter -> fused_LR (PDL link)
    int tl = (pL + pR + SCB - 1) / SCB;
    scatter_LR<<<(tl + 255) / 256, 256>>>(cL, pL, cR, pR);
    launch_pdl(fused_LR, dim3(2 * WARPS_PER_KIND * 32 / 256), dim3(256),
               (cudaStream_t)0, (const float4*)fL, (const float4*)fR, out);

    cudaStreamWaitEvent(0, e_join, 0);

    cudaEventDestroy(e_fork);
    cudaEventDestroy(e_join);
    cudaStreamDestroy(s1);
}